// round 14
// baseline (speedup 1.0000x reference)
#include <cuda_runtime.h>
#include <cuda_bf16.h>
#include <stdint.h>

#define Nn    4096
#define Dd    512
#define D4    128        // Dd/4
#define NE    131072
#define WPR   128
#define SLOTS 128
#define NBA   512        // structure kernel blocks (x256 thr, co-resident)
#define NBB   148        // solve kernel blocks (x1024 thr, 1/SM)
#define RPB   28         // rows per solve block: 148*28 = 4144 >= 4096

// ---------------- scratch (zero-initialized at module load) ----------------
__device__ uint32_t g_bm [Nn * WPR];     // dedupe bitmaps (scatter idempotent)
__device__ uint32_t g_bmT[Nn * WPR];
__device__ int      g_cols [Nn * SLOTS];
__device__ int      g_colsT[Nn * SLOTS];
__device__ int      g_cnt [Nn];
__device__ int      g_cntT[Nn];
__device__ float    g_dinv[Nn];
__device__ float    g_v[Nn];
__device__ float    g_u[Nn], g_u2[Nn];
__device__ float    g_q[Dd];             // zeroed in k_pow1 each call
__device__ float    g_Af[Nn * Dd];       // R fp32 (final-phase base)
__device__ uint2    g_Ab[Nn * D4];       // R bf16 (bulk base + iterate0)
__device__ uint2    g_Xb[Nn * D4];       // X bf16
__device__ uint2    g_bf0[Nn * D4];      // iterate ping
__device__ uint2    g_bf1[Nn * D4];      // iterate pong
__device__ int      g_bar[8];            // barrier counters (cross-reset)
__device__ int      g_qdone;             // q-ready flag (reset in k_structure)

// ---------------- helpers ----------------
__device__ __forceinline__ float4 bf2f4(uint2 r) {
    float2 a = __bfloat1622float2(*(__nv_bfloat162*)&r.x);
    float2 b = __bfloat1622float2(*(__nv_bfloat162*)&r.y);
    return make_float4(a.x, a.y, b.x, b.y);
}
__device__ __forceinline__ uint2 f42bf(float4 x) {
    __nv_bfloat162 p0 = __float22bfloat162_rn(make_float2(x.x, x.y));
    __nv_bfloat162 p1 = __float22bfloat162_rn(make_float2(x.z, x.w));
    uint2 o; o.x = *(uint32_t*)&p0; o.y = *(uint32_t*)&p1;
    return o;
}
// spin grid barrier (all blocks of this kernel co-resident by construction)
__device__ __forceinline__ void gridbar(int idx, int nb) {
    __syncthreads();
    if (threadIdx.x == 0) {
        __threadfence();
        atomicAdd(&g_bar[idx], 1);
        volatile int* p = &g_bar[idx];
        while (*p < nb) {}
    }
    __syncthreads();
}

// gather sum over bf16 rows: s += sum_j dinv[j] * in[j, col]
__device__ __forceinline__ float4 gather_bf(const uint2* __restrict__ in,
                                            const int* __restrict__ cols,
                                            int cnt, int col, float4 s) {
    int k = 0;
    for (; k + 4 <= cnt; k += 4) {
        int j0 = __ldg(&cols[k]),   j1 = __ldg(&cols[k+1]);
        int j2 = __ldg(&cols[k+2]), j3 = __ldg(&cols[k+3]);
        float w0 = __ldg(&g_dinv[j0]), w1 = __ldg(&g_dinv[j1]);
        float w2 = __ldg(&g_dinv[j2]), w3 = __ldg(&g_dinv[j3]);
        float4 v0 = bf2f4(__ldg(&in[(long)j0 * D4 + col]));
        float4 v1 = bf2f4(__ldg(&in[(long)j1 * D4 + col]));
        float4 v2 = bf2f4(__ldg(&in[(long)j2 * D4 + col]));
        float4 v3 = bf2f4(__ldg(&in[(long)j3 * D4 + col]));
        s.x += w0*v0.x + w1*v1.x + w2*v2.x + w3*v3.x;
        s.y += w0*v0.y + w1*v1.y + w2*v2.y + w3*v3.y;
        s.z += w0*v0.z + w1*v1.z + w2*v2.z + w3*v3.z;
        s.w += w0*v0.w + w1*v1.w + w2*v2.w + w3*v3.w;
    }
    for (; k < cnt; k++) {
        int j = __ldg(&cols[k]);
        float w = __ldg(&g_dinv[j]);
        float4 v = bf2f4(__ldg(&in[(long)j * D4 + col]));
        s.x += w*v.x; s.y += w*v.y; s.z += w*v.z; s.w += w*v.w;
    }
    return s;
}

// compact one bitmap row into CSR (warp-collective)
__device__ __forceinline__ void build_row(const uint32_t* __restrict__ rowbm,
                                          int* __restrict__ dst, int row,
                                          int lane, int writeStats,
                                          int* __restrict__ cntArr) {
    uint4 W = ((const uint4*)rowbm)[lane];
    uint32_t w[4] = { W.x, W.y, W.z, W.w };
    int c = __popc(w[0]) + __popc(w[1]) + __popc(w[2]) + __popc(w[3]);
    int incl = c;
#pragma unroll
    for (int d = 1; d < 32; d <<= 1) {
        int t = __shfl_up_sync(0xFFFFFFFFu, incl, d);
        if (lane >= d) incl += t;
    }
    int total = __shfl_sync(0xFFFFFFFFu, incl, 31);
    int off = incl - c;
#pragma unroll
    for (int k = 0; k < 4; k++) {
        uint32_t m = w[k];
        int base = (lane*4 + k) << 5;
        while (m) { int b = __ffs(m) - 1; m &= m - 1; dst[off++] = base + b; }
    }
    if (lane == 0) {
        cntArr[row] = total;
        if (writeStats) {
            float deg = (float)(total + 1);
            g_dinv[row] = rsqrtf(deg);
            g_v[row]    = sqrtf(deg);
        }
    }
}

// ---------------- FUSED structure: scatter -> bar -> build ----------------
__global__ __launch_bounds__(256) void k_structure(const int* __restrict__ ei32) {
    int tid = threadIdx.x;
    int g   = blockIdx.x * 256 + tid;      // 0..131071, one edge each
    if (g == 0) { g_bar[1] = 0; g_bar[2] = 0; g_bar[3] = 0; g_qdone = 0; }

    // dtype sniff: int64 values < 4096 => all odd 32-bit words zero
    int acc = __ldg(&ei32[1])     | __ldg(&ei32[257])   | __ldg(&ei32[1023])
            | __ldg(&ei32[2047])  | __ldg(&ei32[4095])  | __ldg(&ei32[8191])
            | __ldg(&ei32[65535]) | __ldg(&ei32[262143]);
    int s, d;
    if (acc == 0) { s = ei32[2*g]; d = ei32[2*(NE+g)]; }
    else          { s = ei32[g];   d = ei32[NE+g]; }
    atomicOr(&g_bm [s * WPR + (d >> 5)], 1u << (d & 31));
    atomicOr(&g_bmT[d * WPR + (s >> 5)], 1u << (s & 31));

    gridbar(0, NBA);

    int w = g >> 5, lane = tid & 31;       // 4096 warps: warp w builds row w (fwd+T)
    build_row(&g_bm [w * WPR], &g_cols [w * SLOTS], w, lane, 1, g_cnt);
    build_row(&g_bmT[w * WPR], &g_colsT[w * SLOTS], w, lane, 0, g_cntT);
}

// ---------------- side stream ----------------
__global__ void k_x2bf(const float4* __restrict__ x) {
    int i = blockIdx.x * blockDim.x + threadIdx.x;   // 524288
    g_Xb[i] = f42bf(x[i]);
}

__global__ __launch_bounds__(1024) void k_pow1() {
    int row  = blockIdx.x * 32 + (threadIdx.x >> 5);
    int lane = threadIdx.x & 31;
    if (blockIdx.x == 0 && threadIdx.x < Dd) g_q[threadIdx.x] = 0.f;
    int cnt = g_cntT[row];
    const int* cols = &g_colsT[row * SLOTS];
    float s = 0.f;
    for (int k = lane; k < cnt; k += 32) s += g_dinv[cols[k]];   // u = 1
#pragma unroll
    for (int d = 16; d; d >>= 1) s += __shfl_down_sync(0xFFFFFFFFu, s, d);
    if (lane == 0) {
        float di = g_dinv[row];
        g_u2[row] = di * (s + di);
    }
}

__global__ __launch_bounds__(1024) void k_pow(const float* __restrict__ src,
                                              float* __restrict__ dst) {
    int row  = blockIdx.x * 32 + (threadIdx.x >> 5);
    int lane = threadIdx.x & 31;
    int cnt = g_cntT[row];
    const int* cols = &g_colsT[row * SLOTS];
    float s = 0.f;
    for (int k = lane; k < cnt; k += 32) s += g_dinv[cols[k]] * src[cols[k]];
#pragma unroll
    for (int d = 16; d; d >>= 1) s += __shfl_down_sync(0xFFFFFFFFu, s, d);
    if (lane == 0) {
        float di = g_dinv[row];
        dst[row] = di * (s + di * src[row]);
    }
}

__global__ __launch_bounds__(1024) void k_qaccum() {
    __shared__ float sh[Dd];
    int t = threadIdx.x;
    int col2 = t & 255;
    int part = t >> 8;
    int r0 = blockIdx.x * 32 + part * 8;
    float s0 = 0.f, s1 = 0.f;
    const uint32_t* xb32 = (const uint32_t*)g_Xb;
    for (int k = 0; k < 8; k++) {
        float ur = g_u2[r0 + k];
        uint32_t p = __ldg(&xb32[(long)(r0 + k) * 256 + col2]);
        float2 f = __bfloat1622float2(*(__nv_bfloat162*)&p);
        s0 += ur * f.x; s1 += ur * f.y;
    }
    if (part == 0) { sh[2*col2] = s0; sh[2*col2+1] = s1; }
    __syncthreads();
    if (part == 1) { sh[2*col2] += s0; sh[2*col2+1] += s1; }
    __syncthreads();
    if (part == 2) { sh[2*col2] += s0; sh[2*col2+1] += s1; }
    __syncthreads();
    if (part == 3) { sh[2*col2] += s0; sh[2*col2+1] += s1; }
    __syncthreads();
    if (t < Dd) atomicAdd(&g_q[t], sh[t]);
}

// scale q, then raise the q-ready flag
__global__ __launch_bounds__(1024) void k_qscale() {
    __shared__ float sh[32];
    __shared__ float scale;
    int t = threadIdx.x, lane = t & 31, wid = t >> 5;
    float s = 0.f;
    for (int i = t; i < Nn; i += 1024) s += g_u2[i] * g_v[i];
#pragma unroll
    for (int d = 16; d; d >>= 1) s += __shfl_down_sync(0xFFFFFFFFu, s, d);
    if (lane == 0) sh[wid] = s;
    __syncthreads();
    if (t < 32) {
        s = sh[t];
#pragma unroll
        for (int d = 16; d; d >>= 1) s += __shfl_down_sync(0xFFFFFFFFu, s, d);
        if (t == 0) scale = 0.1944f / s;    // 0.6^4 * 1.5 / (u.v)
    }
    __syncthreads();
    if (t < Dd) g_q[t] *= scale;
    __threadfence();                        // each thread publishes its q store
    __syncthreads();
    if (t == 0) atomicExch(&g_qdone, 1);
}

// ---------------- FUSED solve: Rpass -> bulk -> bulk -> final ----------------
__global__ __launch_bounds__(1024) void k_solve(const float4* __restrict__ xf,
                                                float4* __restrict__ yo) {
    int tid = threadIdx.x;
    int blk = blockIdx.x;
    if (blk == 0 && tid == 0) g_bar[0] = 0;   // reset structure's slot for next replay
    int sub = tid >> 7;                        // 8 rows in flight per block
    int col = tid & 127;

    // ---- phase 1: R = (I + 0.5*Ahat)X  (fp32 + bf16 outputs) ----
    for (int si = sub; si < RPB; si += 8) {
        int row = blk * RPB + si;
        if (row < Nn) {
            int cnt = g_cnt[row];
            float di = g_dinv[row];
            const int* cols = &g_cols[row * SLOTS];
            long idx = (long)row * D4 + col;
            float4 xi = __ldg(&xf[idx]);
            float4 s0 = make_float4(di*xi.x, di*xi.y, di*xi.z, di*xi.w);
            float4 s = gather_bf(g_Xb, cols, cnt, col, s0);
            float hd = 0.5f * di;
            float4 o = make_float4(xi.x + hd*s.x, xi.y + hd*s.y,
                                   xi.z + hd*s.z, xi.w + hd*s.w);
            g_Af[idx*4+0] = o.x; g_Af[idx*4+1] = o.y;   // fp32 base (flat)
            g_Af[idx*4+2] = o.z; g_Af[idx*4+3] = o.w;
            g_Ab[idx] = f42bf(o);
        }
    }
    gridbar(1, NBB);

    // ---- phase 2: acc = R + 0.6*Ahat*R ----
    for (int si = sub; si < RPB; si += 8) {
        int row = blk * RPB + si;
        if (row < Nn) {
            int cnt = g_cnt[row];
            float di = g_dinv[row];
            const int* cols = &g_cols[row * SLOTS];
            long idx = (long)row * D4 + col;
            float4 sv = bf2f4(__ldg(&g_Ab[idx]));
            float4 s0 = make_float4(di*sv.x, di*sv.y, di*sv.z, di*sv.w);
            float4 s = gather_bf(g_Ab, cols, cnt, col, s0);
            float4 bs = bf2f4(__ldg(&g_Ab[idx]));
            float bd = 0.6f * di;
            g_bf0[idx] = f42bf(make_float4(bs.x + bd*s.x, bs.y + bd*s.y,
                                           bs.z + bd*s.z, bs.w + bd*s.w));
        }
    }
    gridbar(2, NBB);

    // ---- phase 3: acc = R + 0.6*Ahat*acc ----
    for (int si = sub; si < RPB; si += 8) {
        int row = blk * RPB + si;
        if (row < Nn) {
            int cnt = g_cnt[row];
            float di = g_dinv[row];
            const int* cols = &g_cols[row * SLOTS];
            long idx = (long)row * D4 + col;
            float4 sv = bf2f4(__ldg(&g_bf0[idx]));
            float4 s0 = make_float4(di*sv.x, di*sv.y, di*sv.z, di*sv.w);
            float4 s = gather_bf(g_bf0, cols, cnt, col, s0);
            float4 bs = bf2f4(__ldg(&g_Ab[idx]));
            float bd = 0.6f * di;
            g_bf1[idx] = f42bf(make_float4(bs.x + bd*s.x, bs.y + bd*s.y,
                                           bs.z + bd*s.z, bs.w + bd*s.w));
        }
    }
    gridbar(3, NBB);

    // ---- wait for q (side stream sets g_qdone; no circular dependency) ----
    if (tid == 0) { while (atomicAdd(&g_qdone, 0) == 0) {} }
    __syncthreads();

    // ---- phase 4: Y = 0.4*R + 0.24*Ahat*acc + v*q ----
    for (int si = sub; si < RPB; si += 8) {
        int row = blk * RPB + si;
        if (row < Nn) {
            int cnt = g_cnt[row];
            float di = g_dinv[row];
            const int* cols = &g_cols[row * SLOTS];
            long idx = (long)row * D4 + col;
            float4 sv = bf2f4(__ldg(&g_bf1[idx]));
            float4 s0 = make_float4(di*sv.x, di*sv.y, di*sv.z, di*sv.w);
            float4 s = gather_bf(g_bf1, cols, cnt, col, s0);
            float4 bs = ((const float4*)g_Af)[idx];
            float bd = 0.24f * di;
            float rv = g_v[row];
            float4 q = ((const float4*)g_q)[col];
            yo[idx] = make_float4(0.4f*bs.x + bd*s.x + rv*q.x,
                                  0.4f*bs.y + bd*s.y + rv*q.y,
                                  0.4f*bs.z + bd*s.z + rv*q.z,
                                  0.4f*bs.w + bd*s.w + rv*q.w);
        }
    }
}

// ---------------- launch ----------------
extern "C" void kernel_launch(void* const* d_in, const int* in_sizes, int n_in,
                              void* d_out, int out_size) {
    const float* x    = (const float*)d_in[0];
    const void*  eraw = d_in[1];
    if (in_sizes[0] != Nn * Dd) { x = (const float*)d_in[1]; eraw = d_in[0]; }
    const int* ei32 = (const int*)eraw;
    float4*    yo   = (float4*)d_out;

    float *pu;   cudaGetSymbolAddress((void**)&pu,  g_u);
    float *pu2;  cudaGetSymbolAddress((void**)&pu2, g_u2);

    cudaStream_t s2;
    cudaStreamCreateWithFlags(&s2, cudaStreamNonBlocking);
    cudaEvent_t evF, evB, evX, evJ;
    cudaEventCreateWithFlags(&evF, cudaEventDisableTiming);
    cudaEventCreateWithFlags(&evB, cudaEventDisableTiming);
    cudaEventCreateWithFlags(&evX, cudaEventDisableTiming);
    cudaEventCreateWithFlags(&evJ, cudaEventDisableTiming);

    // legal fork: event from capturing stream first
    cudaEventRecord(evF, 0);
    cudaStreamWaitEvent(s2, evF, 0);

    // side: X->bf16 (depends only on X)
    k_x2bf<<<2048, 256, 0, s2>>>((const float4*)x);
    cudaEventRecord(evX, s2);

    // main: fused scatter+build
    k_structure<<<NBA, 256>>>(ei32);
    cudaEventRecord(evB, 0);

    // side: u/q pipeline (needs build + Xb); qscale raises g_qdone
    cudaStreamWaitEvent(s2, evB, 0);
    k_pow1<<<128, 1024, 0, s2>>>();
    k_pow<<<128, 1024, 0, s2>>>(pu2, pu);
    k_pow<<<128, 1024, 0, s2>>>(pu,  pu2);
    k_qaccum<<<128, 1024, 0, s2>>>();
    k_qscale<<<1, 1024, 0, s2>>>();
    cudaEventRecord(evJ, s2);

    // main: fused solve (joins q via device flag inside)
    cudaStreamWaitEvent(0, evX, 0);
    k_solve<<<NBB, 1024>>>((const float4*)x, yo);

    // join side stream back for capture legality (no critical-path cost)
    cudaStreamWaitEvent(0, evJ, 0);
}

// round 15
// speedup vs baseline: 1.3104x; 1.3104x over previous
#include <cuda_runtime.h>
#include <cuda_bf16.h>
#include <stdint.h>

#define Nn    4096
#define Dd    512
#define D4    128        // Dd/4
#define NE    131072
#define WPR   128
#define SLOTS 128
#define NBA   512        // structure blocks (x256 thr = 131K threads, co-resident)

// ---------------- scratch (zero-initialized at module load) ----------------
__device__ uint32_t g_bm [Nn * WPR];     // dedupe bitmaps (scatter idempotent)
__device__ uint32_t g_bmT[Nn * WPR];
__device__ int      g_cols [Nn * SLOTS];
__device__ int      g_colsT[Nn * SLOTS];
__device__ int      g_cnt [Nn];
__device__ int      g_cntT[Nn];
__device__ float    g_dinv[Nn];
__device__ float    g_v[Nn];
__device__ float    g_u[Nn], g_u2[Nn];
__device__ float    g_q[Dd];             // zeroed in k_pow1 each call
__device__ float    g_Af[Nn * Dd];       // R fp32 (final-pass base)
__device__ uint2    g_Ab[Nn * D4];       // R bf16 (bulk base + iterate0)
__device__ uint2    g_Xb[Nn * D4];       // X bf16
__device__ uint2    g_bf0[Nn * D4];      // iterate ping
__device__ uint2    g_bf1[Nn * D4];      // iterate pong
__device__ int      g_bar[4];            // structure barrier (reset by k_final)

// ---------------- helpers ----------------
__device__ __forceinline__ float4 bf2f4(uint2 r) {
    float2 a = __bfloat1622float2(*(__nv_bfloat162*)&r.x);
    float2 b = __bfloat1622float2(*(__nv_bfloat162*)&r.y);
    return make_float4(a.x, a.y, b.x, b.y);
}
__device__ __forceinline__ uint2 f42bf(float4 x) {
    __nv_bfloat162 p0 = __float22bfloat162_rn(make_float2(x.x, x.y));
    __nv_bfloat162 p1 = __float22bfloat162_rn(make_float2(x.z, x.w));
    uint2 o; o.x = *(uint32_t*)&p0; o.y = *(uint32_t*)&p1;
    return o;
}

// compact one bitmap row into CSR (warp-collective, uint4 coalesced load)
__device__ __forceinline__ void build_row(const uint32_t* __restrict__ rowbm,
                                          int* __restrict__ dst, int row,
                                          int lane, int writeStats,
                                          int* __restrict__ cntArr) {
    uint4 W = ((const uint4*)rowbm)[lane];           // 512B/warp, one transaction
    uint32_t w[4] = { W.x, W.y, W.z, W.w };
    int c = __popc(w[0]) + __popc(w[1]) + __popc(w[2]) + __popc(w[3]);
    int incl = c;
#pragma unroll
    for (int d = 1; d < 32; d <<= 1) {
        int t = __shfl_up_sync(0xFFFFFFFFu, incl, d);
        if (lane >= d) incl += t;
    }
    int total = __shfl_sync(0xFFFFFFFFu, incl, 31);
    int off = incl - c;
#pragma unroll
    for (int k = 0; k < 4; k++) {
        uint32_t m = w[k];
        int base = (lane*4 + k) << 5;
        while (m) { int b = __ffs(m) - 1; m &= m - 1; dst[off++] = base + b; }
    }
    if (lane == 0) {
        cntArr[row] = total;
        if (writeStats) {
            float deg = (float)(total + 1);
            g_dinv[row] = rsqrtf(deg);
            g_v[row]    = sqrtf(deg);
        }
    }
}

// ---------------- FUSED structure: scatter -> gridbar -> build -----------------
// 512x256 = 131K threads, co-resident (chip holds 303K). Only concurrent work is
// k_x2bf (no dependencies, drains in ~3us) -> barrier wait is bounded, no deadlock.
__global__ __launch_bounds__(256) void k_structure(const int* __restrict__ ei32) {
    int tid = threadIdx.x;
    int g   = blockIdx.x * 256 + tid;      // one edge per thread
    // dtype sniff: int64 values < 4096 => all odd 32-bit words zero
    int acc = __ldg(&ei32[1])     | __ldg(&ei32[257])   | __ldg(&ei32[1023])
            | __ldg(&ei32[2047])  | __ldg(&ei32[4095])  | __ldg(&ei32[8191])
            | __ldg(&ei32[65535]) | __ldg(&ei32[262143]);
    int s, d;
    if (acc == 0) { s = ei32[2*g]; d = ei32[2*(NE+g)]; }   // int64 low words
    else          { s = ei32[g];   d = ei32[NE+g]; }       // int32
    atomicOr(&g_bm [s * WPR + (d >> 5)], 1u << (d & 31));
    atomicOr(&g_bmT[d * WPR + (s >> 5)], 1u << (s & 31));

    // grid barrier (slot 0; k_final resets it for the next replay)
    __syncthreads();
    if (tid == 0) {
        __threadfence();
        atomicAdd(&g_bar[0], 1);
        volatile int* p = &g_bar[0];
        while (*p < NBA) {}
    }
    __syncthreads();

    int w = g >> 5, lane = tid & 31;       // 4096 warps: warp w builds row w (fwd+T)
    build_row(&g_bm [w * WPR], &g_cols [w * SLOTS], w, lane, 1, g_cnt);
    build_row(&g_bmT[w * WPR], &g_colsT[w * SLOTS], w, lane, 0, g_cntT);
}

// ---------------- X fp32 -> bf16 (side stream) ----------------
__global__ void k_x2bf(const float4* __restrict__ x) {
    int i = blockIdx.x * blockDim.x + threadIdx.x;   // 524288
    g_Xb[i] = f42bf(x[i]);
}

// ---------------- first power iteration with implicit u = 1; zeroes q ----------
__global__ __launch_bounds__(1024) void k_pow1() {
    int row  = blockIdx.x * 32 + (threadIdx.x >> 5);
    int lane = threadIdx.x & 31;
    if (blockIdx.x == 0 && threadIdx.x < Dd) g_q[threadIdx.x] = 0.f;
    int cnt = g_cntT[row];
    const int* cols = &g_colsT[row * SLOTS];
    float s = 0.f;
    for (int k = lane; k < cnt; k += 32) s += g_dinv[cols[k]];   // u = 1
#pragma unroll
    for (int d = 16; d; d >>= 1) s += __shfl_down_sync(0xFFFFFFFFu, s, d);
    if (lane == 0) {
        float di = g_dinv[row];
        g_u2[row] = di * (s + di);
    }
}

// ---------------- one power iteration (Ahat^T) ----------------
__global__ __launch_bounds__(1024) void k_pow(const float* __restrict__ src,
                                              float* __restrict__ dst) {
    int row  = blockIdx.x * 32 + (threadIdx.x >> 5);
    int lane = threadIdx.x & 31;
    int cnt = g_cntT[row];
    const int* cols = &g_colsT[row * SLOTS];
    float s = 0.f;
    for (int k = lane; k < cnt; k += 32) s += g_dinv[cols[k]] * src[cols[k]];
#pragma unroll
    for (int d = 16; d; d >>= 1) s += __shfl_down_sync(0xFFFFFFFFu, s, d);
    if (lane == 0) {
        float di = g_dinv[row];
        dst[row] = di * (s + di * src[row]);
    }
}

// ---------------- q partial sums (bf16 X), 128 atomics/col ----------------
__global__ __launch_bounds__(1024) void k_qaccum() {
    __shared__ float sh[Dd];
    int t = threadIdx.x;
    int col2 = t & 255;
    int part = t >> 8;
    int r0 = blockIdx.x * 32 + part * 8;
    float s0 = 0.f, s1 = 0.f;
    const uint32_t* xb32 = (const uint32_t*)g_Xb;
    for (int k = 0; k < 8; k++) {
        float ur = g_u2[r0 + k];
        uint32_t p = __ldg(&xb32[(long)(r0 + k) * 256 + col2]);
        float2 f = __bfloat1622float2(*(__nv_bfloat162*)&p);
        s0 += ur * f.x; s1 += ur * f.y;
    }
    if (part == 0) { sh[2*col2] = s0; sh[2*col2+1] = s1; }
    __syncthreads();
    if (part == 1) { sh[2*col2] += s0; sh[2*col2+1] += s1; }
    __syncthreads();
    if (part == 2) { sh[2*col2] += s0; sh[2*col2+1] += s1; }
    __syncthreads();
    if (part == 3) { sh[2*col2] += s0; sh[2*col2+1] += s1; }
    __syncthreads();
    if (t < Dd) atomicAdd(&g_q[t], sh[t]);
}

// ---------------- scale q by 0.6^4 * 1.5 / (u.v) ----------------
__global__ __launch_bounds__(1024) void k_qscale() {
    __shared__ float sh[32];
    __shared__ float scale;
    int t = threadIdx.x, lane = t & 31, wid = t >> 5;
    float s = 0.f;
    for (int i = t; i < Nn; i += 1024) s += g_u2[i] * g_v[i];
#pragma unroll
    for (int d = 16; d; d >>= 1) s += __shfl_down_sync(0xFFFFFFFFu, s, d);
    if (lane == 0) sh[wid] = s;
    __syncthreads();
    if (t < 32) {
        s = sh[t];
#pragma unroll
        for (int d = 16; d; d >>= 1) s += __shfl_down_sync(0xFFFFFFFFu, s, d);
        if (t == 0) scale = 0.1944f / s;    // 0.6^4 * 1.5 / (u.v)
    }
    __syncthreads();
    if (t < Dd) g_q[t] *= scale;
}

// ---------------- R pass: R = (I + 0.5*Ahat)X ----------------
__global__ __launch_bounds__(128) void k_Rpass(
    const float4* __restrict__ xf, const uint2* __restrict__ xb,
    float4* __restrict__ outf, uint2* __restrict__ outb)
{
    int row = blockIdx.x;
    int col = threadIdx.x;
    int cnt = g_cnt[row];
    float di = g_dinv[row];
    const int* cols = &g_cols[row * SLOTS];
    long idx = (long)row * D4 + col;

    float4 xi = __ldg(&xf[idx]);
    float4 s;
    s.x = di * xi.x; s.y = di * xi.y; s.z = di * xi.z; s.w = di * xi.w;

    int k = 0;
    for (; k + 4 <= cnt; k += 4) {
        int j0 = __ldg(&cols[k]),   j1 = __ldg(&cols[k+1]);
        int j2 = __ldg(&cols[k+2]), j3 = __ldg(&cols[k+3]);
        float w0 = __ldg(&g_dinv[j0]), w1 = __ldg(&g_dinv[j1]);
        float w2 = __ldg(&g_dinv[j2]), w3 = __ldg(&g_dinv[j3]);
        float4 v0 = bf2f4(__ldg(&xb[(long)j0 * D4 + col]));
        float4 v1 = bf2f4(__ldg(&xb[(long)j1 * D4 + col]));
        float4 v2 = bf2f4(__ldg(&xb[(long)j2 * D4 + col]));
        float4 v3 = bf2f4(__ldg(&xb[(long)j3 * D4 + col]));
        s.x += w0*v0.x + w1*v1.x + w2*v2.x + w3*v3.x;
        s.y += w0*v0.y + w1*v1.y + w2*v2.y + w3*v3.y;
        s.z += w0*v0.z + w1*v1.z + w2*v2.z + w3*v3.z;
        s.w += w0*v0.w + w1*v1.w + w2*v2.w + w3*v3.w;
    }
    for (; k < cnt; k++) {
        int j = __ldg(&cols[k]);
        float w = __ldg(&g_dinv[j]);
        float4 v = bf2f4(__ldg(&xb[(long)j * D4 + col]));
        s.x += w*v.x; s.y += w*v.y; s.z += w*v.z; s.w += w*v.w;
    }
    float hd = 0.5f * di;
    float4 o;
    o.x = xi.x + hd*s.x;
    o.y = xi.y + hd*s.y;
    o.z = xi.z + hd*s.z;
    o.w = xi.w + hd*s.w;
    outf[idx] = o;
    outb[idx] = f42bf(o);
}

// ---------------- middle bulk pass (all-bf16) ----------------
__global__ __launch_bounds__(128) void k_bulk(
    const uint2* __restrict__ inb, const uint2* __restrict__ baseb,
    uint2* __restrict__ outb)
{
    int row = blockIdx.x;
    int col = threadIdx.x;
    int cnt = g_cnt[row];
    float di = g_dinv[row];
    const int* cols = &g_cols[row * SLOTS];
    long idx = (long)row * D4 + col;

    float4 sv = bf2f4(__ldg(&inb[idx]));
    float4 s;
    s.x = di * sv.x; s.y = di * sv.y; s.z = di * sv.z; s.w = di * sv.w;

    int k = 0;
    for (; k + 4 <= cnt; k += 4) {
        int j0 = __ldg(&cols[k]),   j1 = __ldg(&cols[k+1]);
        int j2 = __ldg(&cols[k+2]), j3 = __ldg(&cols[k+3]);
        float w0 = __ldg(&g_dinv[j0]), w1 = __ldg(&g_dinv[j1]);
        float w2 = __ldg(&g_dinv[j2]), w3 = __ldg(&g_dinv[j3]);
        float4 v0 = bf2f4(__ldg(&inb[(long)j0 * D4 + col]));
        float4 v1 = bf2f4(__ldg(&inb[(long)j1 * D4 + col]));
        float4 v2 = bf2f4(__ldg(&inb[(long)j2 * D4 + col]));
        float4 v3 = bf2f4(__ldg(&inb[(long)j3 * D4 + col]));
        s.x += w0*v0.x + w1*v1.x + w2*v2.x + w3*v3.x;
        s.y += w0*v0.y + w1*v1.y + w2*v2.y + w3*v3.y;
        s.z += w0*v0.z + w1*v1.z + w2*v2.z + w3*v3.z;
        s.w += w0*v0.w + w1*v1.w + w2*v2.w + w3*v3.w;
    }
    for (; k < cnt; k++) {
        int j = __ldg(&cols[k]);
        float w = __ldg(&g_dinv[j]);
        float4 v = bf2f4(__ldg(&inb[(long)j * D4 + col]));
        s.x += w*v.x; s.y += w*v.y; s.z += w*v.z; s.w += w*v.w;
    }
    float4 bs = bf2f4(__ldg(&baseb[idx]));
    float bd = 0.6f * di;
    float4 o;
    o.x = bs.x + bd*s.x; o.y = bs.y + bd*s.y;
    o.z = bs.z + bd*s.z; o.w = bs.w + bd*s.w;
    outb[idx] = f42bf(o);
}

// ---------------- final: Y = 0.4*R + 0.24*Ahat*acc + v_i*q ----------------
__global__ __launch_bounds__(128) void k_final(
    const uint2* __restrict__ inb, const float4* __restrict__ basef,
    float4* __restrict__ out)
{
    if (blockIdx.x == 0 && threadIdx.x == 0) g_bar[0] = 0;  // reset for next replay
    int row = blockIdx.x;
    int col = threadIdx.x;
    int cnt = g_cnt[row];
    float di = g_dinv[row];
    const int* cols = &g_cols[row * SLOTS];
    long idx = (long)row * D4 + col;

    float4 sv = bf2f4(__ldg(&inb[idx]));
    float4 s;
    s.x = di * sv.x; s.y = di * sv.y; s.z = di * sv.z; s.w = di * sv.w;

    int k = 0;
    for (; k + 4 <= cnt; k += 4) {
        int j0 = __ldg(&cols[k]),   j1 = __ldg(&cols[k+1]);
        int j2 = __ldg(&cols[k+2]), j3 = __ldg(&cols[k+3]);
        float w0 = __ldg(&g_dinv[j0]), w1 = __ldg(&g_dinv[j1]);
        float w2 = __ldg(&g_dinv[j2]), w3 = __ldg(&g_dinv[j3]);
        float4 v0 = bf2f4(__ldg(&inb[(long)j0 * D4 + col]));
        float4 v1 = bf2f4(__ldg(&inb[(long)j1 * D4 + col]));
        float4 v2 = bf2f4(__ldg(&inb[(long)j2 * D4 + col]));
        float4 v3 = bf2f4(__ldg(&inb[(long)j3 * D4 + col]));
        s.x += w0*v0.x + w1*v1.x + w2*v2.x + w3*v3.x;
        s.y += w0*v0.y + w1*v1.y + w2*v2.y + w3*v3.y;
        s.z += w0*v0.z + w1*v1.z + w2*v2.z + w3*v3.z;
        s.w += w0*v0.w + w1*v1.w + w2*v2.w + w3*v3.w;
    }
    for (; k < cnt; k++) {
        int j = __ldg(&cols[k]);
        float w = __ldg(&g_dinv[j]);
        float4 v = bf2f4(__ldg(&inb[(long)j * D4 + col]));
        s.x += w*v.x; s.y += w*v.y; s.z += w*v.z; s.w += w*v.w;
    }
    float4 bs = __ldg(&basef[idx]);
    float bd = 0.24f * di;
    float rv = g_v[row];
    float4 q = ((const float4*)g_q)[col];
    float4 o;
    o.x = 0.4f*bs.x + bd*s.x + rv*q.x;
    o.y = 0.4f*bs.y + bd*s.y + rv*q.y;
    o.z = 0.4f*bs.z + bd*s.z + rv*q.z;
    o.w = 0.4f*bs.w + bd*s.w + rv*q.w;
    out[idx] = o;
}

// ---------------- launch ----------------
extern "C" void kernel_launch(void* const* d_in, const int* in_sizes, int n_in,
                              void* d_out, int out_size) {
    const float* x    = (const float*)d_in[0];
    const void*  eraw = d_in[1];
    if (in_sizes[0] != Nn * Dd) { x = (const float*)d_in[1]; eraw = d_in[0]; }
    const int* ei32 = (const int*)eraw;
    float4*    yo   = (float4*)d_out;

    float *pAf;  cudaGetSymbolAddress((void**)&pAf, g_Af);
    uint2 *pAb;  cudaGetSymbolAddress((void**)&pAb, g_Ab);
    uint2 *pXb;  cudaGetSymbolAddress((void**)&pXb, g_Xb);
    uint2 *pbf0; cudaGetSymbolAddress((void**)&pbf0, g_bf0);
    uint2 *pbf1; cudaGetSymbolAddress((void**)&pbf1, g_bf1);
    float *pu;   cudaGetSymbolAddress((void**)&pu,  g_u);
    float *pu2;  cudaGetSymbolAddress((void**)&pu2, g_u2);

    cudaStream_t s2;
    cudaStreamCreateWithFlags(&s2, cudaStreamNonBlocking);
    cudaEvent_t evF, evB, evX, evJ;
    cudaEventCreateWithFlags(&evF, cudaEventDisableTiming);
    cudaEventCreateWithFlags(&evB, cudaEventDisableTiming);
    cudaEventCreateWithFlags(&evX, cudaEventDisableTiming);
    cudaEventCreateWithFlags(&evJ, cudaEventDisableTiming);

    // legal fork: event from capturing stream first
    cudaEventRecord(evF, 0);
    cudaStreamWaitEvent(s2, evF, 0);

    // side: X->bf16 (depends only on X; drains fast, bounded barrier impact)
    k_x2bf<<<2048, 256, 0, s2>>>((const float4*)x);
    cudaEventRecord(evX, s2);

    // main: fused scatter + CSR build
    k_structure<<<NBA, 256>>>(ei32);
    cudaEventRecord(evB, 0);

    // side: u/q pipeline (needs build + Xb)
    cudaStreamWaitEvent(s2, evB, 0);
    k_pow1<<<128, 1024, 0, s2>>>();               // u=1 implicit -> g_u2; zeroes q
    k_pow<<<128, 1024, 0, s2>>>(pu2, pu);
    k_pow<<<128, 1024, 0, s2>>>(pu,  pu2);        // final u in g_u2
    k_qaccum<<<128, 1024, 0, s2>>>();
    k_qscale<<<1, 1024, 0, s2>>>();
    cudaEventRecord(evJ, s2);

    // main: heavy passes (need Xb)
    cudaStreamWaitEvent(0, evX, 0);
    k_Rpass<<<Nn, 128>>>((const float4*)x, pXb, (float4*)pAf, pAb);
    k_bulk<<<Nn, 128>>>(pAb,  pAb, pbf0);
    k_bulk<<<Nn, 128>>>(pbf0, pAb, pbf1);

    // join, then final
    cudaStreamWaitEvent(0, evJ, 0);
    k_final<<<Nn, 128>>>(pbf1, (const float4*)pAf, yo);
}

// round 16
// speedup vs baseline: 1.3514x; 1.0313x over previous
#include <cuda_runtime.h>
#include <cuda_bf16.h>
#include <stdint.h>

#define Nn    4096
#define Dd    512
#define D4    128        // Dd/4
#define NE    131072
#define WPR   128
#define SLOTS 128
#define SB    32         // side-stream blocks (small footprint: ~22% of SMs)

// ---------------- scratch (zero-initialized at module load) ----------------
__device__ uint32_t g_bm [Nn * WPR];     // dedupe bitmaps (scatter idempotent)
__device__ uint32_t g_bmT[Nn * WPR];
__device__ int      g_cols [Nn * SLOTS];
__device__ int      g_colsT[Nn * SLOTS];
__device__ int      g_cnt [Nn];
__device__ int      g_cntT[Nn];
__device__ float    g_dinv[Nn];
__device__ float    g_v[Nn];
__device__ float    g_u[Nn], g_u2[Nn];
__device__ float    g_q[Dd];             // zeroed in k_pow1 each call
__device__ float    g_Af[Nn * Dd];       // R fp32 (final-pass base)
__device__ uint2    g_Ab[Nn * D4];       // R bf16 (bulk base + iterate0)
__device__ uint2    g_Xb[Nn * D4];       // X bf16
__device__ uint2    g_bf0[Nn * D4];      // iterate ping
__device__ uint2    g_bf1[Nn * D4];      // iterate pong

// ---------------- helpers ----------------
__device__ __forceinline__ float4 bf2f4(uint2 r) {
    float2 a = __bfloat1622float2(*(__nv_bfloat162*)&r.x);
    float2 b = __bfloat1622float2(*(__nv_bfloat162*)&r.y);
    return make_float4(a.x, a.y, b.x, b.y);
}
__device__ __forceinline__ uint2 f42bf(float4 x) {
    __nv_bfloat162 p0 = __float22bfloat162_rn(make_float2(x.x, x.y));
    __nv_bfloat162 p1 = __float22bfloat162_rn(make_float2(x.z, x.w));
    uint2 o; o.x = *(uint32_t*)&p0; o.y = *(uint32_t*)&p1;
    return o;
}

// ---------------- scatter (idempotent; per-thread dtype sniff) ----------------
__global__ void k_scatter2(const int* __restrict__ ei32) {
    int e = blockIdx.x * blockDim.x + threadIdx.x;
    if (e >= NE) return;
    // int64 little-endian values < 4096 => ALL odd 32-bit words zero.
    int acc = __ldg(&ei32[1])     | __ldg(&ei32[257])   | __ldg(&ei32[1023])
            | __ldg(&ei32[2047])  | __ldg(&ei32[4095])  | __ldg(&ei32[8191])
            | __ldg(&ei32[65535]) | __ldg(&ei32[262143]);
    int s, d;
    if (acc == 0) { s = ei32[2*e]; d = ei32[2*(NE+e)]; }   // int64 low words
    else          { s = ei32[e];   d = ei32[NE+e]; }       // int32
    atomicOr(&g_bm [s * WPR + (d >> 5)], 1u << (d & 31));
    atomicOr(&g_bmT[d * WPR + (s >> 5)], 1u << (s & 31));
}

// ---------------- CSR build: fwd rows [0,Nn), transpose rows [Nn,2Nn) ----------
__global__ void k_build() {
    int warp = (blockIdx.x * blockDim.x + threadIdx.x) >> 5;   // 0..8191
    int lane = threadIdx.x & 31;
    int fwd = (warp < Nn);
    int row = fwd ? warp : warp - Nn;
    const uint32_t* rowbm = fwd ? &g_bm[row * WPR] : &g_bmT[row * WPR];
    int* dst  = fwd ? &g_cols[row * SLOTS] : &g_colsT[row * SLOTS];
    uint4 W = ((const uint4*)rowbm)[lane];           // coalesced 512B/warp
    uint32_t w[4] = { W.x, W.y, W.z, W.w };
    int c = __popc(w[0]) + __popc(w[1]) + __popc(w[2]) + __popc(w[3]);
    int incl = c;
#pragma unroll
    for (int d = 1; d < 32; d <<= 1) {
        int t = __shfl_up_sync(0xFFFFFFFFu, incl, d);
        if (lane >= d) incl += t;
    }
    int total = __shfl_sync(0xFFFFFFFFu, incl, 31);
    int off = incl - c;
#pragma unroll
    for (int k = 0; k < 4; k++) {
        uint32_t m = w[k];
        int base = (lane*4 + k) << 5;
        while (m) { int b = __ffs(m) - 1; m &= m - 1; dst[off++] = base + b; }
    }
    if (lane == 0) {
        if (fwd) {
            g_cnt[row] = total;
            float deg = (float)(total + 1);
            g_dinv[row] = rsqrtf(deg);
            g_v[row]    = sqrtf(deg);
        } else {
            g_cntT[row] = total;
        }
    }
}

// ---------------- X fp32 -> bf16 (side stream) ----------------
__global__ void k_x2bf(const float4* __restrict__ x) {
    int i = blockIdx.x * blockDim.x + threadIdx.x;   // 524288
    g_Xb[i] = f42bf(x[i]);
}

// ---------------- first power iteration, u = 1 implicit; zeroes q ----------
// 32 blocks x 1024: warp handles 4 rows sequentially (latency-bound, hidden)
__global__ __launch_bounds__(1024) void k_pow1() {
    int wid  = threadIdx.x >> 5;
    int lane = threadIdx.x & 31;
    if (blockIdx.x == 0 && threadIdx.x < Dd) g_q[threadIdx.x] = 0.f;
    for (int row = blockIdx.x * (Nn / SB) + wid; row < (blockIdx.x + 1) * (Nn / SB);
         row += 32) {
        int cnt = g_cntT[row];
        const int* cols = &g_colsT[row * SLOTS];
        float s = 0.f;
        for (int k = lane; k < cnt; k += 32) s += g_dinv[cols[k]];   // u = 1
#pragma unroll
        for (int d = 16; d; d >>= 1) s += __shfl_down_sync(0xFFFFFFFFu, s, d);
        if (lane == 0) {
            float di = g_dinv[row];
            g_u2[row] = di * (s + di);
        }
    }
}

// ---------------- one power iteration (Ahat^T), 32 blocks ----------------
__global__ __launch_bounds__(1024) void k_pow(const float* __restrict__ src,
                                              float* __restrict__ dst) {
    int wid  = threadIdx.x >> 5;
    int lane = threadIdx.x & 31;
    for (int row = blockIdx.x * (Nn / SB) + wid; row < (blockIdx.x + 1) * (Nn / SB);
         row += 32) {
        int cnt = g_cntT[row];
        const int* cols = &g_colsT[row * SLOTS];
        float s = 0.f;
        for (int k = lane; k < cnt; k += 32) s += g_dinv[cols[k]] * src[cols[k]];
#pragma unroll
        for (int d = 16; d; d >>= 1) s += __shfl_down_sync(0xFFFFFFFFu, s, d);
        if (lane == 0) {
            float di = g_dinv[row];
            dst[row] = di * (s + di * src[row]);
        }
    }
}

// ---------------- q partial sums (bf16 X), 32 blocks -> 32 atomics/col ---------
__global__ __launch_bounds__(1024) void k_qaccum() {
    __shared__ float sh[Dd];
    int t = threadIdx.x;
    int col2 = t & 255;                  // 256 bf16x2 pairs = 512 cols
    int part = t >> 8;                   // 4 partitions x 32 rows each
    int r0 = blockIdx.x * (Nn / SB) + part * 32;
    float s0 = 0.f, s1 = 0.f;
    const uint32_t* xb32 = (const uint32_t*)g_Xb;
    for (int k = 0; k < 32; k++) {
        float ur = g_u2[r0 + k];
        uint32_t p = __ldg(&xb32[(long)(r0 + k) * 256 + col2]);
        float2 f = __bfloat1622float2(*(__nv_bfloat162*)&p);
        s0 += ur * f.x; s1 += ur * f.y;
    }
    if (part == 0) { sh[2*col2] = s0; sh[2*col2+1] = s1; }
    __syncthreads();
    if (part == 1) { sh[2*col2] += s0; sh[2*col2+1] += s1; }
    __syncthreads();
    if (part == 2) { sh[2*col2] += s0; sh[2*col2+1] += s1; }
    __syncthreads();
    if (part == 3) { sh[2*col2] += s0; sh[2*col2+1] += s1; }
    __syncthreads();
    if (t < Dd) atomicAdd(&g_q[t], sh[t]);
}

// ---------------- scale q by 0.6^4 * 1.5 / (u.v) ----------------
__global__ __launch_bounds__(1024) void k_qscale() {
    __shared__ float sh[32];
    __shared__ float scale;
    int t = threadIdx.x, lane = t & 31, wid = t >> 5;
    float s = 0.f;
    for (int i = t; i < Nn; i += 1024) s += g_u2[i] * g_v[i];
#pragma unroll
    for (int d = 16; d; d >>= 1) s += __shfl_down_sync(0xFFFFFFFFu, s, d);
    if (lane == 0) sh[wid] = s;
    __syncthreads();
    if (t < 32) {
        s = sh[t];
#pragma unroll
        for (int d = 16; d; d >>= 1) s += __shfl_down_sync(0xFFFFFFFFu, s, d);
        if (t == 0) scale = 0.1944f / s;    // 0.6^4 * 1.5 / (u.v)
    }
    __syncthreads();
    if (t < Dd) g_q[t] *= scale;
}

// ---------------- R pass: R = (I + 0.5*Ahat)X ----------------
__global__ __launch_bounds__(128) void k_Rpass(
    const float4* __restrict__ xf, const uint2* __restrict__ xb,
    float4* __restrict__ outf, uint2* __restrict__ outb)
{
    int row = blockIdx.x;
    int col = threadIdx.x;
    int cnt = g_cnt[row];
    float di = g_dinv[row];
    const int* cols = &g_cols[row * SLOTS];
    long idx = (long)row * D4 + col;

    float4 xi = __ldg(&xf[idx]);
    float4 s;
    s.x = di * xi.x; s.y = di * xi.y; s.z = di * xi.z; s.w = di * xi.w;

    int k = 0;
    for (; k + 4 <= cnt; k += 4) {
        int j0 = __ldg(&cols[k]),   j1 = __ldg(&cols[k+1]);
        int j2 = __ldg(&cols[k+2]), j3 = __ldg(&cols[k+3]);
        float w0 = __ldg(&g_dinv[j0]), w1 = __ldg(&g_dinv[j1]);
        float w2 = __ldg(&g_dinv[j2]), w3 = __ldg(&g_dinv[j3]);
        float4 v0 = bf2f4(__ldg(&xb[(long)j0 * D4 + col]));
        float4 v1 = bf2f4(__ldg(&xb[(long)j1 * D4 + col]));
        float4 v2 = bf2f4(__ldg(&xb[(long)j2 * D4 + col]));
        float4 v3 = bf2f4(__ldg(&xb[(long)j3 * D4 + col]));
        s.x += w0*v0.x + w1*v1.x + w2*v2.x + w3*v3.x;
        s.y += w0*v0.y + w1*v1.y + w2*v2.y + w3*v3.y;
        s.z += w0*v0.z + w1*v1.z + w2*v2.z + w3*v3.z;
        s.w += w0*v0.w + w1*v1.w + w2*v2.w + w3*v3.w;
    }
    for (; k < cnt; k++) {
        int j = __ldg(&cols[k]);
        float w = __ldg(&g_dinv[j]);
        float4 v = bf2f4(__ldg(&xb[(long)j * D4 + col]));
        s.x += w*v.x; s.y += w*v.y; s.z += w*v.z; s.w += w*v.w;
    }
    float hd = 0.5f * di;
    float4 o;
    o.x = xi.x + hd*s.x;
    o.y = xi.y + hd*s.y;
    o.z = xi.z + hd*s.z;
    o.w = xi.w + hd*s.w;
    outf[idx] = o;
    outb[idx] = f42bf(o);
}

// ---------------- middle bulk pass (all-bf16) ----------------
__global__ __launch_bounds__(128) void k_bulk(
    const uint2* __restrict__ inb, const uint2* __restrict__ baseb,
    uint2* __restrict__ outb)
{
    int row = blockIdx.x;
    int col = threadIdx.x;
    int cnt = g_cnt[row];
    float di = g_dinv[row];
    const int* cols = &g_cols[row * SLOTS];
    long idx = (long)row * D4 + col;

    float4 sv = bf2f4(__ldg(&inb[idx]));
    float4 s;
    s.x = di * sv.x; s.y = di * sv.y; s.z = di * sv.z; s.w = di * sv.w;

    int k = 0;
    for (; k + 4 <= cnt; k += 4) {
        int j0 = __ldg(&cols[k]),   j1 = __ldg(&cols[k+1]);
        int j2 = __ldg(&cols[k+2]), j3 = __ldg(&cols[k+3]);
        float w0 = __ldg(&g_dinv[j0]), w1 = __ldg(&g_dinv[j1]);
        float w2 = __ldg(&g_dinv[j2]), w3 = __ldg(&g_dinv[j3]);
        float4 v0 = bf2f4(__ldg(&inb[(long)j0 * D4 + col]));
        float4 v1 = bf2f4(__ldg(&inb[(long)j1 * D4 + col]));
        float4 v2 = bf2f4(__ldg(&inb[(long)j2 * D4 + col]));
        float4 v3 = bf2f4(__ldg(&inb[(long)j3 * D4 + col]));
        s.x += w0*v0.x + w1*v1.x + w2*v2.x + w3*v3.x;
        s.y += w0*v0.y + w1*v1.y + w2*v2.y + w3*v3.y;
        s.z += w0*v0.z + w1*v1.z + w2*v2.z + w3*v3.z;
        s.w += w0*v0.w + w1*v1.w + w2*v2.w + w3*v3.w;
    }
    for (; k < cnt; k++) {
        int j = __ldg(&cols[k]);
        float w = __ldg(&g_dinv[j]);
        float4 v = bf2f4(__ldg(&inb[(long)j * D4 + col]));
        s.x += w*v.x; s.y += w*v.y; s.z += w*v.z; s.w += w*v.w;
    }
    float4 bs = bf2f4(__ldg(&baseb[idx]));
    float bd = 0.6f * di;
    float4 o;
    o.x = bs.x + bd*s.x; o.y = bs.y + bd*s.y;
    o.z = bs.z + bd*s.z; o.w = bs.w + bd*s.w;
    outb[idx] = f42bf(o);
}

// ---------------- final: Y = 0.4*R + 0.24*Ahat*acc + v_i*q ----------------
__global__ __launch_bounds__(128) void k_final(
    const uint2* __restrict__ inb, const float4* __restrict__ basef,
    float4* __restrict__ out)
{
    int row = blockIdx.x;
    int col = threadIdx.x;
    int cnt = g_cnt[row];
    float di = g_dinv[row];
    const int* cols = &g_cols[row * SLOTS];
    long idx = (long)row * D4 + col;

    float4 sv = bf2f4(__ldg(&inb[idx]));
    float4 s;
    s.x = di * sv.x; s.y = di * sv.y; s.z = di * sv.z; s.w = di * sv.w;

    int k = 0;
    for (; k + 4 <= cnt; k += 4) {
        int j0 = __ldg(&cols[k]),   j1 = __ldg(&cols[k+1]);
        int j2 = __ldg(&cols[k+2]), j3 = __ldg(&cols[k+3]);
        float w0 = __ldg(&g_dinv[j0]), w1 = __ldg(&g_dinv[j1]);
        float w2 = __ldg(&g_dinv[j2]), w3 = __ldg(&g_dinv[j3]);
        float4 v0 = bf2f4(__ldg(&inb[(long)j0 * D4 + col]));
        float4 v1 = bf2f4(__ldg(&inb[(long)j1 * D4 + col]));
        float4 v2 = bf2f4(__ldg(&inb[(long)j2 * D4 + col]));
        float4 v3 = bf2f4(__ldg(&inb[(long)j3 * D4 + col]));
        s.x += w0*v0.x + w1*v1.x + w2*v2.x + w3*v3.x;
        s.y += w0*v0.y + w1*v1.y + w2*v2.y + w3*v3.y;
        s.z += w0*v0.z + w1*v1.z + w2*v2.z + w3*v3.z;
        s.w += w0*v0.w + w1*v1.w + w2*v2.w + w3*v3.w;
    }
    for (; k < cnt; k++) {
        int j = __ldg(&cols[k]);
        float w = __ldg(&g_dinv[j]);
        float4 v = bf2f4(__ldg(&inb[(long)j * D4 + col]));
        s.x += w*v.x; s.y += w*v.y; s.z += w*v.z; s.w += w*v.w;
    }
    float4 bs = __ldg(&basef[idx]);
    float bd = 0.24f * di;
    float rv = g_v[row];
    float4 q = ((const float4*)g_q)[col];
    float4 o;
    o.x = 0.4f*bs.x + bd*s.x + rv*q.x;
    o.y = 0.4f*bs.y + bd*s.y + rv*q.y;
    o.z = 0.4f*bs.z + bd*s.z + rv*q.z;
    o.w = 0.4f*bs.w + bd*s.w + rv*q.w;
    out[idx] = o;
}

// ---------------- launch ----------------
extern "C" void kernel_launch(void* const* d_in, const int* in_sizes, int n_in,
                              void* d_out, int out_size) {
    const float* x    = (const float*)d_in[0];
    const void*  eraw = d_in[1];
    if (in_sizes[0] != Nn * Dd) { x = (const float*)d_in[1]; eraw = d_in[0]; }
    const int* ei32 = (const int*)eraw;
    float4*    yo   = (float4*)d_out;

    float *pAf;  cudaGetSymbolAddress((void**)&pAf, g_Af);
    uint2 *pAb;  cudaGetSymbolAddress((void**)&pAb, g_Ab);
    uint2 *pXb;  cudaGetSymbolAddress((void**)&pXb, g_Xb);
    uint2 *pbf0; cudaGetSymbolAddress((void**)&pbf0, g_bf0);
    uint2 *pbf1; cudaGetSymbolAddress((void**)&pbf1, g_bf1);
    float *pu;   cudaGetSymbolAddress((void**)&pu,  g_u);
    float *pu2;  cudaGetSymbolAddress((void**)&pu2, g_u2);

    cudaStream_t s2;
    cudaStreamCreateWithFlags(&s2, cudaStreamNonBlocking);
    cudaEvent_t evF, evB, evX, evJ;
    cudaEventCreateWithFlags(&evF, cudaEventDisableTiming);
    cudaEventCreateWithFlags(&evB, cudaEventDisableTiming);
    cudaEventCreateWithFlags(&evX, cudaEventDisableTiming);
    cudaEventCreateWithFlags(&evJ, cudaEventDisableTiming);

    // legal fork: event from capturing stream first
    cudaEventRecord(evF, 0);
    cudaStreamWaitEvent(s2, evF, 0);

    // side: X->bf16 (depends only on X)
    k_x2bf<<<2048, 256, 0, s2>>>((const float4*)x);
    cudaEventRecord(evX, s2);

    // main: scatter (idempotent) + CSR build
    k_scatter2<<<NE / 256, 256>>>(ei32);
    k_build<<<1024, 256>>>();
    cudaEventRecord(evB, 0);

    // side: u/q pipeline at SMALL grids (32 blocks: ~22% SM footprint,
    // latency-bound work stays hidden without starving the main passes)
    cudaStreamWaitEvent(s2, evB, 0);
    k_pow1<<<SB, 1024, 0, s2>>>();                // u=1 implicit -> g_u2; zeroes q
    k_pow<<<SB, 1024, 0, s2>>>(pu2, pu);
    k_pow<<<SB, 1024, 0, s2>>>(pu,  pu2);         // final u in g_u2
    k_qaccum<<<SB, 1024, 0, s2>>>();
    k_qscale<<<1, 1024, 0, s2>>>();
    cudaEventRecord(evJ, s2);

    // main: heavy passes (need Xb)
    cudaStreamWaitEvent(0, evX, 0);
    k_Rpass<<<Nn, 128>>>((const float4*)x, pXb, (float4*)pAf, pAb);
    k_bulk<<<Nn, 128>>>(pAb,  pAb, pbf0);
    k_bulk<<<Nn, 128>>>(pbf0, pAb, pbf1);

    // join, then final
    cudaStreamWaitEvent(0, evJ, 0);
    k_final<<<Nn, 128>>>(pbf1, (const float4*)pAf, yo);
}